// round 2
// baseline (speedup 1.0000x reference)
#include <cuda_runtime.h>
#include <math.h>

// Problem constants
#define S        2048
#define ROWS     65536            // 2*16*2048
#define TN       32               // t-tile per GEMM block
#define KC       32               // k-chunk

// Scratch (allocation-free rule: __device__ globals)
__device__ int   g_idx[ROWS];
__device__ float g_gather[ROWS];

// ---------------------------------------------------------------------------
// Kernel A: one block per row. Copy x->out (float4) while reducing
// first-occurrence argmax of the row. 256 threads, 8 floats/thread.
// ---------------------------------------------------------------------------
__global__ void __launch_bounds__(256)
copy_argmax_kernel(const float* __restrict__ x, float* __restrict__ out)
{
    const int row = blockIdx.x;
    const float4* __restrict__ xr = (const float4*)(x + (size_t)row * S);
    float4* __restrict__ orow     = (float4*)(out + (size_t)row * S);

    const int t = threadIdx.x;

    float best = -INFINITY;
    int   bidx = 0;

    // Two float4s per thread; indices scanned in increasing order within
    // thread, strict '>' keeps the first occurrence.
    #pragma unroll
    for (int i = 0; i < 2; i++) {
        const int e = t + i * 256;          // float4 index in row (0..511)
        float4 v = xr[e];
        orow[e] = v;
        const int base = e * 4;
        if (v.x > best) { best = v.x; bidx = base + 0; }
        if (v.y > best) { best = v.y; bidx = base + 1; }
        if (v.z > best) { best = v.z; bidx = base + 2; }
        if (v.w > best) { best = v.w; bidx = base + 3; }
    }

    // Warp reduction with first-occurrence tie-break (smaller index wins ties)
    #pragma unroll
    for (int off = 16; off > 0; off >>= 1) {
        float ov = __shfl_down_sync(0xFFFFFFFFu, best, off);
        int   oi = __shfl_down_sync(0xFFFFFFFFu, bidx, off);
        if (ov > best || (ov == best && oi < bidx)) { best = ov; bidx = oi; }
    }

    __shared__ float sv[8];
    __shared__ int   si[8];
    const int lane = t & 31;
    const int warp = t >> 5;
    if (lane == 0) { sv[warp] = best; si[warp] = bidx; }
    __syncthreads();

    if (warp == 0) {
        best = (lane < 8) ? sv[lane] : -INFINITY;
        bidx = (lane < 8) ? si[lane] : 0x7FFFFFFF;
        #pragma unroll
        for (int off = 4; off > 0; off >>= 1) {
            float ov = __shfl_down_sync(0xFFFFFFFFu, best, off);
            int   oi = __shfl_down_sync(0xFFFFFFFFu, bidx, off);
            if (ov > best || (ov == best && oi < bidx)) { best = ov; bidx = oi; }
        }
        if (lane == 0) {
            g_idx[row]    = bidx;
            g_gather[row] = best;
        }
    }
}

// ---------------------------------------------------------------------------
// Kernel B: y[m][t] = gelu( sum_s g[m][s] * W[t][s] + b[t] ), m in [0,32),
// t-tile of 32 per block (64 blocks). Epilogue scatters directly into out:
//   out[(m*S + t)*S + idx[m*S + t]] = y[m][t]
// ---------------------------------------------------------------------------
__global__ void __launch_bounds__(256)
gemm_gelu_scatter_kernel(const float* __restrict__ W,
                         const float* __restrict__ bias,
                         float* __restrict__ out)
{
    __shared__ float gs[32][KC + 1];   // [m][k]
    __shared__ float ws[TN][KC + 1];   // [n][k]

    const int tile_n = blockIdx.x * TN;
    const int tid = threadIdx.x;
    const int m   = tid & 31;          // output row
    const int nb  = tid >> 5;          // 0..7 -> 4 consecutive n each

    // Cooperative-load coordinates: 1024 elems per tile, float4 per thread
    const int lrow = tid >> 3;         // 0..31
    const int lcol = (tid & 7) * 4;    // 0,4,...,28

    float acc0 = 0.f, acc1 = 0.f, acc2 = 0.f, acc3 = 0.f;

    for (int k0 = 0; k0 < S; k0 += KC) {
        float4 gv = *(const float4*)(g_gather + (size_t)lrow * S + k0 + lcol);
        gs[lrow][lcol + 0] = gv.x; gs[lrow][lcol + 1] = gv.y;
        gs[lrow][lcol + 2] = gv.z; gs[lrow][lcol + 3] = gv.w;

        float4 wv = *(const float4*)(W + (size_t)(tile_n + lrow) * S + k0 + lcol);
        ws[lrow][lcol + 0] = wv.x; ws[lrow][lcol + 1] = wv.y;
        ws[lrow][lcol + 2] = wv.z; ws[lrow][lcol + 3] = wv.w;

        __syncthreads();

        #pragma unroll
        for (int k = 0; k < KC; k++) {
            const float a = gs[m][k];
            acc0 = fmaf(a, ws[nb * 4 + 0][k], acc0);
            acc1 = fmaf(a, ws[nb * 4 + 1][k], acc1);
            acc2 = fmaf(a, ws[nb * 4 + 2][k], acc2);
            acc3 = fmaf(a, ws[nb * 4 + 3][k], acc3);
        }
        __syncthreads();
    }

    float accs[4] = { acc0, acc1, acc2, acc3 };
    #pragma unroll
    for (int i = 0; i < 4; i++) {
        const int t = tile_n + nb * 4 + i;
        float v = accs[i] + bias[t];
        // exact GELU (erf form), matches approximate=False
        float ge = 0.5f * v * (1.0f + erff(v * 0.70710678118654752f));
        const size_t r = (size_t)m * S + t;   // row index (b,h,s)=(m,t)
        out[r * (size_t)S + (size_t)g_idx[r]] = ge;
    }
}

// ---------------------------------------------------------------------------
extern "C" void kernel_launch(void* const* d_in, const int* in_sizes, int n_in,
                              void* d_out, int out_size)
{
    const float* x    = (const float*)d_in[0];   // [2,16,2048,2048]
    const float* W    = (const float*)d_in[1];   // [2048,2048]
    const float* bias = (const float*)d_in[2];   // [2048]
    float* out        = (float*)d_out;

    copy_argmax_kernel<<<ROWS, 256>>>(x, out);
    gemm_gelu_scatter_kernel<<<S / TN, 256>>>(W, bias, out);
}

// round 4
// speedup vs baseline: 1.3249x; 1.3249x over previous
#include <cuda_runtime.h>
#include <math.h>

// Problem constants
#define S        2048
#define ROWS     65536            // 2*16*2048 rows of x; also 32*2048 gemm outputs
#define TNB      64               // t-tile per partial-GEMM block
#define KCB      64               // k-chunk per partial-GEMM block
#define KSPLIT   32               // 2048 / KCB

// Scratch (allocation-free rule: __device__ globals)
__device__ int   g_idx[ROWS];
__device__ float g_gather[ROWS];
__device__ float g_part[KSPLIT * ROWS];   // 8 MB fp32 partials [ks][m][t]

// ---------------------------------------------------------------------------
// Kernel A: one block per row. Copy x->out (float4) while reducing
// first-occurrence argmax of the row. 256 threads, 8 floats/thread.
// (measured ~6.9 TB/s — at HBM roofline; unchanged)
// ---------------------------------------------------------------------------
__global__ void __launch_bounds__(256)
copy_argmax_kernel(const float* __restrict__ x, float* __restrict__ out)
{
    const int row = blockIdx.x;
    const float4* __restrict__ xr = (const float4*)(x + (size_t)row * S);
    float4* __restrict__ orow     = (float4*)(out + (size_t)row * S);

    const int t = threadIdx.x;

    float best = -INFINITY;
    int   bidx = 0;

    #pragma unroll
    for (int i = 0; i < 2; i++) {
        const int e = t + i * 256;          // float4 index in row (0..511)
        float4 v = xr[e];
        orow[e] = v;
        const int base = e * 4;
        if (v.x > best) { best = v.x; bidx = base + 0; }
        if (v.y > best) { best = v.y; bidx = base + 1; }
        if (v.z > best) { best = v.z; bidx = base + 2; }
        if (v.w > best) { best = v.w; bidx = base + 3; }
    }

    // Warp reduction with first-occurrence tie-break (smaller index wins ties)
    #pragma unroll
    for (int off = 16; off > 0; off >>= 1) {
        float ov = __shfl_down_sync(0xFFFFFFFFu, best, off);
        int   oi = __shfl_down_sync(0xFFFFFFFFu, bidx, off);
        if (ov > best || (ov == best && oi < bidx)) { best = ov; bidx = oi; }
    }

    __shared__ float sv[8];
    __shared__ int   si[8];
    const int lane = t & 31;
    const int warp = t >> 5;
    if (lane == 0) { sv[warp] = best; si[warp] = bidx; }
    __syncthreads();

    if (warp == 0) {
        best = (lane < 8) ? sv[lane] : -INFINITY;
        bidx = (lane < 8) ? si[lane] : 0x7FFFFFFF;
        #pragma unroll
        for (int off = 4; off > 0; off >>= 1) {
            float ov = __shfl_down_sync(0xFFFFFFFFu, best, off);
            int   oi = __shfl_down_sync(0xFFFFFFFFu, bidx, off);
            if (ov > best || (ov == best && oi < bidx)) { best = ov; bidx = oi; }
        }
        if (lane == 0) {
            g_idx[row]    = bidx;
            g_gather[row] = best;
        }
    }
}

// ---------------------------------------------------------------------------
// Kernel B1: k-split partial GEMM. Grid (S/TNB=32, KSPLIT=32) = 1024 blocks,
// 128 threads. Block computes partial C[32][64] over one 64-wide k-chunk.
// Register tile 4m x 4t per thread (16 FMA : 8 LDS per k).
// ---------------------------------------------------------------------------
__global__ void __launch_bounds__(128)
gemm_partial_kernel(const float* __restrict__ W)
{
    __shared__ float gs[32][KCB + 1];    // [m][k], pad for conflict-free fill
    __shared__ float ws[TNB][KCB + 1];   // [t][k]

    const int t0  = blockIdx.x * TNB;
    const int k0  = blockIdx.y * KCB;
    const int tid = threadIdx.x;

    // Fill gs: 32 rows x 64 cols. thread -> row tid>>2, 16-col segment (tid&3)*16
    {
        const int m  = tid >> 2;
        const int cb = (tid & 3) * 16;
        #pragma unroll
        for (int j = 0; j < 4; j++) {
            float4 v = *(const float4*)(g_gather + (size_t)m * S + k0 + cb + j * 4);
            gs[m][cb + j*4 + 0] = v.x; gs[m][cb + j*4 + 1] = v.y;
            gs[m][cb + j*4 + 2] = v.z; gs[m][cb + j*4 + 3] = v.w;
        }
    }
    // Fill ws: 64 rows x 64 cols. thread -> row tid>>1, 32-col segment (tid&1)*32
    {
        const int t  = tid >> 1;
        const int cb = (tid & 1) * 32;
        #pragma unroll
        for (int j = 0; j < 8; j++) {
            float4 v = *(const float4*)(W + (size_t)(t0 + t) * S + k0 + cb + j * 4);
            ws[t][cb + j*4 + 0] = v.x; ws[t][cb + j*4 + 1] = v.y;
            ws[t][cb + j*4 + 2] = v.z; ws[t][cb + j*4 + 3] = v.w;
        }
    }
    __syncthreads();

    const int m0  = (tid & 7) * 4;    // 8 m-groups
    const int tn0 = (tid >> 3) * 4;   // 16 t-groups

    float acc[4][4] = {};

    #pragma unroll 8
    for (int k = 0; k < KCB; k++) {
        const float a0 = gs[m0 + 0][k];
        const float a1 = gs[m0 + 1][k];
        const float a2 = gs[m0 + 2][k];
        const float a3 = gs[m0 + 3][k];
        const float w0 = ws[tn0 + 0][k];
        const float w1 = ws[tn0 + 1][k];
        const float w2 = ws[tn0 + 2][k];
        const float w3 = ws[tn0 + 3][k];
        acc[0][0] = fmaf(a0, w0, acc[0][0]); acc[0][1] = fmaf(a0, w1, acc[0][1]);
        acc[0][2] = fmaf(a0, w2, acc[0][2]); acc[0][3] = fmaf(a0, w3, acc[0][3]);
        acc[1][0] = fmaf(a1, w0, acc[1][0]); acc[1][1] = fmaf(a1, w1, acc[1][1]);
        acc[1][2] = fmaf(a1, w2, acc[1][2]); acc[1][3] = fmaf(a1, w3, acc[1][3]);
        acc[2][0] = fmaf(a2, w0, acc[2][0]); acc[2][1] = fmaf(a2, w1, acc[2][1]);
        acc[2][2] = fmaf(a2, w2, acc[2][2]); acc[2][3] = fmaf(a2, w3, acc[2][3]);
        acc[3][0] = fmaf(a3, w0, acc[3][0]); acc[3][1] = fmaf(a3, w1, acc[3][1]);
        acc[3][2] = fmaf(a3, w2, acc[3][2]); acc[3][3] = fmaf(a3, w3, acc[3][3]);
    }

    float* p = g_part + (size_t)blockIdx.y * ROWS;
    #pragma unroll
    for (int i = 0; i < 4; i++) {
        #pragma unroll
        for (int j = 0; j < 4; j++) {
            p[(size_t)(m0 + i) * S + t0 + tn0 + j] = acc[i][j];
        }
    }
}

// ---------------------------------------------------------------------------
// Kernel B2: reduce KSPLIT partials (fixed order -> deterministic), + bias,
// exact-erf GELU, scatter into out at argmax positions. 65536 threads.
// ---------------------------------------------------------------------------
__global__ void __launch_bounds__(256)
reduce_gelu_scatter_kernel(const float* __restrict__ bias,
                           float* __restrict__ out)
{
    const int r = blockIdx.x * 256 + threadIdx.x;   // 0..65535  (= m*S + t)
    float s = 0.0f;
    #pragma unroll
    for (int ks = 0; ks < KSPLIT; ks++)
        s += g_part[(size_t)ks * ROWS + r];

    const int t = r & (S - 1);
    const float v  = s + bias[t];
    const float ge = 0.5f * v * (1.0f + erff(v * 0.70710678118654752f));
    out[(size_t)r * S + (size_t)g_idx[r]] = ge;
}

// ---------------------------------------------------------------------------
extern "C" void kernel_launch(void* const* d_in, const int* in_sizes, int n_in,
                              void* d_out, int out_size)
{
    const float* x    = (const float*)d_in[0];   // [2,16,2048,2048]
    const float* W    = (const float*)d_in[1];   // [2048,2048]
    const float* bias = (const float*)d_in[2];   // [2048]
    float* out        = (float*)d_out;

    copy_argmax_kernel<<<ROWS, 256>>>(x, out);
    gemm_partial_kernel<<<dim3(S / TNB, KSPLIT), 128>>>(W);
    reduce_gelu_scatter_kernel<<<ROWS / 256, 256>>>(bias, out);
}